// round 15
// baseline (speedup 1.0000x reference)
#include <cuda_runtime.h>
#include <cuda_fp16.h>
#include <cstdint>

// DepthAwareConv2d as fp16 mma.sync (m16n8k16, fp32 accum) implicit GEMM.
// R15 = R14 with the staging stride bug fixed: a 16B cp.async moves 4 b32
// words (4 px), so each 64-px row needs 16 segs at word stride 4 (R14 used 4
// segs at word stride 16, leaving 48/64 px uninitialized -> NaN).
// CTA = 128 o x 64 px (warp tile 32x32, 2048 CTAs), 32 accum regs,
// __launch_bounds__(256,3) targets 3 CTAs/SM. Full K staged up front
// (8 B-stages, 62 KB), A direct from global fragment-major.
// B row: 80 words = [0..2] pad, [3] left halo, [4..67] data, [68] right halo,
// [69..79] pad; cpair stride 248 words (read banks {0,24,16,8}).

#define Nn 4
#define Cc 128
#define Oo 256
#define Hh 128
#define Ww 128
#define CG 16                // channels per group (= MMA K)
#define NCG (Cc / CG)        // 8
#define RS  80               // B row stride in b32
#define CPS 248              // B cpair-block stride in b32 (3*RS + 8 skew)

// A image per (o-tile 128, c-group): [tap 9][mt 8][lane 32][r 4] b32
#define ASZ 9216
// B image per c-group: 8 cpair blocks x CPS b32
#define BSZ (8 * CPS)        // 1984 b32 = 7936 B

// grid split for the merged prep kernel
#define GXD (Nn * (Cc / 2) * Hh * Ww / 4 / 256)   // 4096 blocks
#define GWA ((2 * NCG * ASZ + 255) / 256)         // 576 blocks

__device__ uint32_t g_xdt2[Nn * (Cc / 2) * Hh * Ww];   // half2(xd[2c], xd[2c+1])
__device__ uint32_t g_wta2[2 * NCG * ASZ];             // fragment-major fp16 weights

// ----------------------------- helpers --------------------------------------
__device__ __forceinline__ void cp_async16z(uint32_t dst, const void* src, uint32_t sz) {
    asm volatile("cp.async.cg.shared.global [%0], [%1], 16, %2;"
                 :: "r"(dst), "l"(src), "r"(sz) : "memory");
}
__device__ __forceinline__ void cp_async4z(uint32_t dst, const void* src, uint32_t sz) {
    asm volatile("cp.async.ca.shared.global [%0], [%1], 4, %2;"
                 :: "r"(dst), "l"(src), "r"(sz) : "memory");
}
__device__ __forceinline__ void cp_commit() {
    asm volatile("cp.async.commit_group;" ::: "memory");
}
template <int N>
__device__ __forceinline__ void cp_wait() {
    asm volatile("cp.async.wait_group %0;" :: "n"(N) : "memory");
}
__device__ __forceinline__ void cp_wait_n(int n) {
    switch (n) {
        case 0: cp_wait<0>(); break;
        case 1: cp_wait<1>(); break;
        case 2: cp_wait<2>(); break;
        case 3: cp_wait<3>(); break;
        case 4: cp_wait<4>(); break;
        case 5: cp_wait<5>(); break;
        case 6: cp_wait<6>(); break;
        default: cp_wait<7>(); break;
    }
}
__device__ __forceinline__ uint32_t lds32(uint32_t addr) {
    uint32_t v;
    asm volatile("ld.shared.b32 %0, [%1];" : "=r"(v) : "r"(addr));
    return v;
}
__device__ __forceinline__ void mma_f16(float& c0, float& c1, float& c2, float& c3,
                                        uint32_t a0, uint32_t a1, uint32_t a2, uint32_t a3,
                                        uint32_t b0, uint32_t b1) {
    asm("mma.sync.aligned.m16n8k16.row.col.f32.f16.f16.f32 "
        "{%0,%1,%2,%3}, {%4,%5,%6,%7}, {%8,%9}, {%0,%1,%2,%3};"
        : "+f"(c0), "+f"(c1), "+f"(c2), "+f"(c3)
        : "r"(a0), "r"(a1), "r"(a2), "r"(a3), "r"(b0), "r"(b1));
}
__device__ __forceinline__ uint32_t pack_h2(float lo, float hi) {
    __half2 h = __floats2half2_rn(lo, hi);
    return *reinterpret_cast<uint32_t*>(&h);
}

// --------------------------- merged prep kernel ------------------------------
__global__ void prep_all_kernel(const float* __restrict__ x,
                                const float* __restrict__ dep,
                                const float* __restrict__ w)
{
    if (blockIdx.x < GXD) {
        const int i = (blockIdx.x * 256 + threadIdx.x) * 4;
        const int n  = i >> 20;
        const int cp = (i >> 14) & 63;
        const int hw = i & 16383;
        const float4 x0 = *reinterpret_cast<const float4*>(x + (((size_t)(n * Cc + 2 * cp)) << 14) + hw);
        const float4 x1 = *reinterpret_cast<const float4*>(x + (((size_t)(n * Cc + 2 * cp + 1)) << 14) + hw);
        const float4 dv = *reinterpret_cast<const float4*>(dep + ((size_t)n << 14) + hw);
        uint4 r;
        r.x = pack_h2(x0.x * dv.x, x1.x * dv.x);
        r.y = pack_h2(x0.y * dv.y, x1.y * dv.y);
        r.z = pack_h2(x0.z * dv.z, x1.z * dv.z);
        r.w = pack_h2(x0.w * dv.w, x1.w * dv.w);
        *reinterpret_cast<uint4*>(g_xdt2 + i) = r;
    } else {
        const int i = (blockIdx.x - GXD) * 256 + threadIdx.x;
        if (i >= 2 * NCG * ASZ) return;
        const int r    = i & 3;
        const int lane = (i >> 2) & 31;
        const int mt   = (i >> 7) & 7;
        const int tap  = (i >> 10) % 9;
        const int rest = i / ASZ;
        const int cg   = rest & (NCG - 1);
        const int ot   = rest >> 3;
        const int o  = ot * 128 + mt * 16 + (r & 1) * 8 + (lane >> 2);
        const int cb = cg * CG + (lane & 3) * 2 + ((r >> 1) << 3);
        g_wta2[i] = pack_h2(w[(o * Cc + cb) * 9 + tap], w[(o * Cc + cb + 1) * 9 + tap]);
    }
}

// ------------------------------- main kernel --------------------------------
// grid (Nn*Hh*2, 2), 256 threads. CTA: M=128 o x N=64 px (half image row).
// 8 warps: warpM = wid>>1 (32 o each), warpN = wid&1 (32 px each).
__global__ __launch_bounds__(256, 3)
void conv_f16_mma_kernel(const float* __restrict__ bias, float* __restrict__ out)
{
    extern __shared__ uint32_t smem[];
    const uint32_t sBb = (uint32_t)__cvta_generic_to_shared(smem);

    const int tid   = threadIdx.x;
    const int lane  = tid & 31;
    const int wid   = tid >> 5;
    const int warpM = wid >> 1;                  // 0..3
    const int warpN = wid & 1;                   // 0..1

    const int pix = blockIdx.x * 64;
    const int n   = pix >> 14;
    const int y   = (pix >> 7) & (Hh - 1);
    const int x0  = pix & 127;                   // 0 or 64
    const int ot  = blockIdx.y;
    const int oBase = ot * 128;

    const uint32_t* xsrc = g_xdt2 + ((size_t)n << 20);
    const uint4*    aV   = reinterpret_cast<const uint4*>(g_wta2 + (size_t)(ot * NCG) * ASZ);

    // ---- per-thread staging roles (flattened idx space, 432 ops/cg) ----
    // idx in [0,384): data copy, row = idx>>4 (=cp*3+rr), seg = idx&15 (4 px).
    // idx in [384,432): halo copy, h = idx-384, row = h>>1, side = h&1.
    // iter 0: idx = tid (always data). iter 1: idx = 256+tid.
    const int rowD0 = tid >> 4,          segD0 = tid & 15;
    const int cpD0  = rowD0 / 3,         rrD0  = rowD0 - cpD0 * 3;
    const int idx1  = 256 + tid;
    const bool isD1 = idx1 < 384;                       // tid < 128
    const bool isH1 = !isD1 && (idx1 < 432);            // tid in [128,176)
    const int rowD1 = idx1 >> 4,         segD1 = idx1 & 15;
    const int cpD1  = rowD1 / 3,         rrD1  = rowD1 - cpD1 * 3;
    const int h1    = idx1 - 384;
    const int rowH1 = h1 >> 1,           sideH1 = h1 & 1;
    const int cpH1  = rowH1 / 3,         rrH1   = rowH1 - cpH1 * 3;

    // ---- stage ALL 8 c-groups up front (8 commit groups) ----
    #pragma unroll
    for (int cg = 0; cg < NCG; ++cg) {
        const uint32_t dB = sBb + cg * (BSZ * 4);
        {   // iter 0: data, row rowD0, 4 px at seg*4
            const int yy = y + rrD0 - 1;
            const bool inb = (unsigned)yy < (unsigned)Hh;
            const int yc = inb ? yy : 0;
            const uint32_t* src = xsrc + (((size_t)(cg * 8 + cpD0)) << 14) + (yc << 7) + x0 + segD0 * 4;
            cp_async16z(dB + (cpD0 * CPS + rrD0 * RS + 4 + segD0 * 4) * 4, src, inb ? 16u : 0u);
        }
        if (isD1) {
            const int yy = y + rrD1 - 1;
            const bool inb = (unsigned)yy < (unsigned)Hh;
            const int yc = inb ? yy : 0;
            const uint32_t* src = xsrc + (((size_t)(cg * 8 + cpD1)) << 14) + (yc << 7) + x0 + segD1 * 4;
            cp_async16z(dB + (cpD1 * CPS + rrD1 * RS + 4 + segD1 * 4) * 4, src, inb ? 16u : 0u);
        } else if (isH1) {
            const int yy = y + rrH1 - 1;
            const int gx = sideH1 ? x0 + 64 : x0 - 1;
            const bool inb = ((unsigned)yy < (unsigned)Hh) & ((unsigned)gx < (unsigned)Ww);
            const int yc = inb ? yy : 0;
            const int xc = inb ? gx : 0;
            const uint32_t* src = xsrc + (((size_t)(cg * 8 + cpH1)) << 14) + (yc << 7) + xc;
            cp_async4z(dB + (cpH1 * CPS + rrH1 * RS + (sideH1 ? 68 : 3)) * 4, src, inb ? 4u : 0u);
        }
        cp_commit();
    }

    float acc[2][4][4];
    #pragma unroll
    for (int m = 0; m < 2; m++)
        #pragma unroll
        for (int j = 0; j < 4; j++)
            #pragma unroll
            for (int r = 0; r < 4; r++) acc[m][j][r] = 0.0f;

    // per-thread B base: cpair = lane%4, slot = 3 + warpN*32 + lane/4 (+dx,+dy*RS)
    const uint32_t bTh = ((lane & 3) * CPS + 3 + warpN * 32 + (lane >> 2)) * 4;

    #pragma unroll
    for (int cg = 0; cg < NCG; ++cg) {
        cp_wait_n(NCG - 1 - cg);      // own copies of stage cg complete
        __syncthreads();              // ... and everyone's, published

        const uint32_t bBase0 = sBb + cg * (BSZ * 4) + bTh;       // cpairs 0..3
        const uint32_t bBase1 = bBase0 + 4 * CPS * 4;             // cpairs 4..7
        const uint4* aCg = aV + (size_t)cg * (ASZ / 4);

        #pragma unroll
        for (int tap = 0; tap < 9; tap++) {
            const int dy = tap / 3, dx = tap - dy * 3;
            const uint32_t doff = (dy * RS + dx) * 4;

            uint32_t b0[4], b1[4];
            #pragma unroll
            for (int j = 0; j < 4; j++) {
                b0[j] = lds32(bBase0 + doff + j * 32);   // +8 px per n-subtile
                b1[j] = lds32(bBase1 + doff + j * 32);
            }
            uint4 av[2];
            #pragma unroll
            for (int m = 0; m < 2; m++)
                av[m] = __ldg(aCg + (tap * 8 + warpM * 2 + m) * 32 + lane);

            #pragma unroll
            for (int m = 0; m < 2; m++)
                #pragma unroll
                for (int j = 0; j < 4; j++)
                    mma_f16(acc[m][j][0], acc[m][j][1], acc[m][j][2], acc[m][j][3],
                            av[m].x, av[m].y, av[m].z, av[m].w, b0[j], b1[j]);
        }
    }

    // ---- epilogue: +bias, direct STG.64 ----
    const int g = lane >> 2, t = lane & 3;
    #pragma unroll
    for (int m = 0; m < 2; m++) {
        const int oLo = oBase + warpM * 32 + m * 16 + g;
        const float bLo = bias[oLo], bHi = bias[oLo + 8];
        const size_t rowLo = (((size_t)(n * Oo + oLo))     << 14) + (y << 7);
        const size_t rowHi = (((size_t)(n * Oo + oLo + 8)) << 14) + (y << 7);
        #pragma unroll
        for (int j = 0; j < 4; j++) {
            const int xb = x0 + warpN * 32 + j * 8 + 2 * t;
            float2 lo = make_float2(acc[m][j][0] + bLo, acc[m][j][1] + bLo);
            float2 hi = make_float2(acc[m][j][2] + bHi, acc[m][j][3] + bHi);
            *reinterpret_cast<float2*>(out + rowLo + xb) = lo;
            *reinterpret_cast<float2*>(out + rowHi + xb) = hi;
        }
    }
}

// ------------------------------- launcher -----------------------------------
extern "C" void kernel_launch(void* const* d_in, const int* in_sizes, int n_in,
                              void* d_out, int out_size)
{
    const float* x    = (const float*)d_in[0];
    const float* dep  = (const float*)d_in[1];
    // d_in[2] = camera_params (unused by the math)
    const float* w    = (const float*)d_in[3];
    const float* bias = (const float*)d_in[4];
    float* out = (float*)d_out;

    constexpr int SMEM_BYTES = NCG * BSZ * 4;   // 63,488 B

    static bool attr_set = false;
    if (!attr_set) {
        cudaFuncSetAttribute(conv_f16_mma_kernel,
                             cudaFuncAttributeMaxDynamicSharedMemorySize, SMEM_BYTES);
        attr_set = true;
    }

    prep_all_kernel<<<GXD + GWA, 256>>>(x, dep, w);

    dim3 grid(Nn * Hh * 2, 2, 1);   // 2048 CTAs (half-row tiles)
    conv_f16_mma_kernel<<<grid, 256, SMEM_BYTES>>>(bias, out);
}

// round 16
// speedup vs baseline: 1.0852x; 1.0852x over previous
#include <cuda_runtime.h>
#include <cuda_fp16.h>
#include <cstdint>

// DepthAwareConv2d as fp16 mma.sync (m16n8k16, fp32 accum) implicit GEMM.
// R16 = R13 with NST=5 B-buffers (65.3 KB/CTA instead of 104.4 KB) so the L1D
// carveout leaves ~97 KB: the 36.9 KB/c-group A tile (read x4 by warpN warps
// via __ldg) becomes L1-resident instead of L2-served (~250cyc -> ~39cyc).
// cg 5..7 restage buffers 0..2 in-loop with depth-4 lookahead (wait is free).

#define Nn 4
#define Cc 128
#define Oo 256
#define Hh 128
#define Ww 128
#define CG 16                // channels per group (= MMA K)
#define NCG (Cc / CG)        // 8
#define RS2 136              // B row stride in b32 units (conflict-free)
#define NST 5                // B buffers

// A image per (o-tile 128, c-group): [tap 9][mt 8][lane 32][r 4] b32
#define ASZ 9216
// B image per c-group: 8 cpairs x 3 rows x RS2 b32
#define BSZ (8 * 3 * RS2)    // 3264 b32 = 13,056 B

// grid split for the merged prep kernel
#define GXD (Nn * (Cc / 2) * Hh * Ww / 4 / 256)   // 4096 blocks
#define GWA ((2 * NCG * ASZ + 255) / 256)         // 576 blocks

__device__ uint32_t g_xdt2[Nn * (Cc / 2) * Hh * Ww];   // half2(xd[2c], xd[2c+1])
__device__ uint32_t g_wta2[2 * NCG * ASZ];             // fragment-major fp16 weights

// ----------------------------- helpers --------------------------------------
__device__ __forceinline__ void cp_async16z(uint32_t dst, const void* src, uint32_t sz) {
    asm volatile("cp.async.cg.shared.global [%0], [%1], 16, %2;"
                 :: "r"(dst), "l"(src), "r"(sz) : "memory");
}
__device__ __forceinline__ void cp_commit() {
    asm volatile("cp.async.commit_group;" ::: "memory");
}
template <int N>
__device__ __forceinline__ void cp_wait() {
    asm volatile("cp.async.wait_group %0;" :: "n"(N) : "memory");
}
__device__ __forceinline__ void cp_wait_n(int n) {
    switch (n) {
        case 0: cp_wait<0>(); break;
        case 1: cp_wait<1>(); break;
        case 2: cp_wait<2>(); break;
        case 3: cp_wait<3>(); break;
        default: cp_wait<4>(); break;
    }
}
__device__ __forceinline__ uint32_t lds32(uint32_t addr) {
    uint32_t v;
    asm volatile("ld.shared.b32 %0, [%1];" : "=r"(v) : "r"(addr));
    return v;
}
__device__ __forceinline__ void mma_f16(float& c0, float& c1, float& c2, float& c3,
                                        uint32_t a0, uint32_t a1, uint32_t a2, uint32_t a3,
                                        uint32_t b0, uint32_t b1) {
    asm("mma.sync.aligned.m16n8k16.row.col.f32.f16.f16.f32 "
        "{%0,%1,%2,%3}, {%4,%5,%6,%7}, {%8,%9}, {%0,%1,%2,%3};"
        : "+f"(c0), "+f"(c1), "+f"(c2), "+f"(c3)
        : "r"(a0), "r"(a1), "r"(a2), "r"(a3), "r"(b0), "r"(b1));
}
__device__ __forceinline__ uint32_t pack_h2(float lo, float hi) {
    __half2 h = __floats2half2_rn(lo, hi);
    return *reinterpret_cast<uint32_t*>(&h);
}

// --------------------------- merged prep kernel ------------------------------
// Blocks [0, GXD): xd pack.  Blocks [GXD, GXD+GWA): weight permute.
__global__ void prep_all_kernel(const float* __restrict__ x,
                                const float* __restrict__ dep,
                                const float* __restrict__ w)
{
    if (blockIdx.x < GXD) {
        const int i = (blockIdx.x * 256 + threadIdx.x) * 4;
        const int n  = i >> 20;
        const int cp = (i >> 14) & 63;
        const int hw = i & 16383;
        const float4 x0 = *reinterpret_cast<const float4*>(x + (((size_t)(n * Cc + 2 * cp)) << 14) + hw);
        const float4 x1 = *reinterpret_cast<const float4*>(x + (((size_t)(n * Cc + 2 * cp + 1)) << 14) + hw);
        const float4 dv = *reinterpret_cast<const float4*>(dep + ((size_t)n << 14) + hw);
        uint4 r;
        r.x = pack_h2(x0.x * dv.x, x1.x * dv.x);
        r.y = pack_h2(x0.y * dv.y, x1.y * dv.y);
        r.z = pack_h2(x0.z * dv.z, x1.z * dv.z);
        r.w = pack_h2(x0.w * dv.w, x1.w * dv.w);
        *reinterpret_cast<uint4*>(g_xdt2 + i) = r;
    } else {
        const int i = (blockIdx.x - GXD) * 256 + threadIdx.x;
        if (i >= 2 * NCG * ASZ) return;
        const int r    = i & 3;
        const int lane = (i >> 2) & 31;
        const int mt   = (i >> 7) & 7;
        const int tap  = (i >> 10) % 9;
        const int rest = i / ASZ;
        const int cg   = rest & (NCG - 1);
        const int ot   = rest >> 3;
        const int o  = ot * 128 + mt * 16 + (r & 1) * 8 + (lane >> 2);
        const int cb = cg * CG + (lane & 3) * 2 + ((r >> 1) << 3);
        g_wta2[i] = pack_h2(w[(o * Cc + cb) * 9 + tap], w[(o * Cc + cb + 1) * 9 + tap]);
    }
}

// ------------------------------- main kernel --------------------------------
// grid (Nn*Hh, 2), 256 threads. CTA: M=128 o, N=128 px (one image row), all K.
// SMEM: B-only, NST=5 buffers (buf = cg % 5; cg 5..7 restage bufs 0..2).
// B row: data x at b32 [4..131], halo x=-1 at [3], x=128 at [132];
// filler [0..2],[133..135] zeroed once. A direct via ld.global.nc.v4 (L1-res).
__global__ __launch_bounds__(256, 2)
void conv_f16_mma_kernel(const float* __restrict__ bias, float* __restrict__ out)
{
    extern __shared__ uint32_t smem[];
    const uint32_t sBb = (uint32_t)__cvta_generic_to_shared(smem);

    const int tid   = threadIdx.x;
    const int lane  = tid & 31;
    const int wid   = tid >> 5;
    const int warpM = wid >> 2;                  // 0..1
    const int warpN = wid & 3;                   // 0..3

    const int pix = blockIdx.x * 128;
    const int n   = pix >> 14;
    const int y   = (pix >> 7) & (Hh - 1);
    const int ot  = blockIdx.y;
    const int oBase = ot * 128;

    const uint32_t* xsrc = g_xdt2 + ((size_t)n << 20);
    const uint4*    aV   = reinterpret_cast<const uint4*>(g_wta2 + (size_t)(ot * NCG) * ASZ);

    // ---- zero halo/filler pads in all 5 B buffers (5 x 24 rows x 8 slots) ----
    for (int idx = tid; idx < NST * 192; idx += 256) {
        const int buf = idx / 192, rem = idx % 192;
        const int row = rem >> 3, p = rem & 7;
        smem[buf * BSZ + row * RS2 + (p < 4 ? p : 128 + p)] = 0u;
    }

    // ---- B staging: one c-group into buffer `buf` (16B cp.async.cg) ----
    auto stageB = [&](int cg, int buf) {
        const uint32_t dB = sBb + buf * (BSZ * 4);
        #pragma unroll
        for (int i = 0; i < 3; i++) {                    // 768 x 16B
            const int idx = i * 256 + tid;
            const int pair = idx >> 5, seg = idx & 31;   // pair = cpair*3 + row
            const int cp = pair / 3, rr = pair - cp * 3;
            const int yy = y + rr - 1;
            const bool inb = (unsigned)yy < (unsigned)Hh;
            const int yc = inb ? yy : 0;
            const uint32_t* src = xsrc + (((size_t)(cg * 8 + cp)) << 14) + (yc << 7) + seg * 4;
            cp_async16z(dB + (pair * RS2 + 4 + seg * 4) * 4, src, inb ? 16u : 0u);
        }
        cp_commit();
    };

    float acc[4][4][4];
    #pragma unroll
    for (int m = 0; m < 4; m++)
        #pragma unroll
        for (int j = 0; j < 4; j++)
            #pragma unroll
            for (int r = 0; r < 4; r++) acc[m][j][r] = 0.0f;

    // per-thread B base: cpair = lane%4, pixel = warpN*32 + lane/4, x shift -1
    const uint32_t bTh = ((lane & 3) * 3 * RS2 + 4 + warpN * 32 + (lane >> 2) - 1) * 4;

    // upfront: stage cg 0..4 (5 commit groups)
    #pragma unroll
    for (int cg = 0; cg < NST; ++cg) stageB(cg, cg);

    #pragma unroll
    for (int cg = 0; cg < NCG; ++cg) {
        const int buf = (cg < NST) ? cg : cg - NST;

        cp_wait_n(min(NST - 1, NCG - 1 - cg));   // own copies of stage cg done
        __syncthreads();                         // ... and everyone's, published

        const uint32_t bBase0 = sBb + buf * (BSZ * 4) + bTh;      // cpair = lane%4
        const uint32_t bBase1 = bBase0 + 4 * 3 * RS2 * 4;         // cpair + 4
        const uint4* aCg = aV + (size_t)cg * (ASZ / 4);

        #pragma unroll
        for (int tap = 0; tap < 9; tap++) {
            const int dy = tap / 3, dx = tap - dy * 3;
            const uint32_t doff = (dy * RS2 + dx) * 4;

            uint32_t b0[4], b1[4];
            #pragma unroll
            for (int j = 0; j < 4; j++) {
                b0[j] = lds32(bBase0 + doff + j * 32);   // +8 px per n-subtile
                b1[j] = lds32(bBase1 + doff + j * 32);
            }
            uint4 av[4];
            #pragma unroll
            for (int m = 0; m < 4; m++)
                av[m] = __ldg(aCg + (tap * 8 + warpM * 4 + m) * 32 + lane);

            #pragma unroll
            for (int m = 0; m < 4; m++)
                #pragma unroll
                for (int j = 0; j < 4; j++)
                    mma_f16(acc[m][j][0], acc[m][j][1], acc[m][j][2], acc[m][j][3],
                            av[m].x, av[m].y, av[m].z, av[m].w, b0[j], b1[j]);
        }

        // restage buffer just consumed with cg+5 (only cg = 0,1,2)
        if (cg + NST < NCG) {
            __syncthreads();                     // all warps done reading buf
            stageB(cg + NST, buf);
        }
    }

    // ---- epilogue: +bias, direct STG.64 ----
    const int g = lane >> 2, t = lane & 3;
    #pragma unroll
    for (int m = 0; m < 4; m++) {
        const int oLo = oBase + warpM * 64 + m * 16 + g;
        const float bLo = bias[oLo], bHi = bias[oLo + 8];
        const size_t rowLo = (((size_t)(n * Oo + oLo))     << 14) + (y << 7);
        const size_t rowHi = (((size_t)(n * Oo + oLo + 8)) << 14) + (y << 7);
        #pragma unroll
        for (int j = 0; j < 4; j++) {
            const int xb = warpN * 32 + j * 8 + 2 * t;
            float2 lo = make_float2(acc[m][j][0] + bLo, acc[m][j][1] + bLo);
            float2 hi = make_float2(acc[m][j][2] + bHi, acc[m][j][3] + bHi);
            *reinterpret_cast<float2*>(out + rowLo + xb) = lo;
            *reinterpret_cast<float2*>(out + rowHi + xb) = hi;
        }
    }
}

// ------------------------------- launcher -----------------------------------
extern "C" void kernel_launch(void* const* d_in, const int* in_sizes, int n_in,
                              void* d_out, int out_size)
{
    const float* x    = (const float*)d_in[0];
    const float* dep  = (const float*)d_in[1];
    // d_in[2] = camera_params (unused by the math)
    const float* w    = (const float*)d_in[3];
    const float* bias = (const float*)d_in[4];
    float* out = (float*)d_out;

    constexpr int SMEM_BYTES = NST * BSZ * 4;   // 65,280 B

    static bool attr_set = false;
    if (!attr_set) {
        cudaFuncSetAttribute(conv_f16_mma_kernel,
                             cudaFuncAttributeMaxDynamicSharedMemorySize, SMEM_BYTES);
        attr_set = true;
    }

    prep_all_kernel<<<GXD + GWA, 256>>>(x, dep, w);

    dim3 grid(Nn * Hh, 2, 1);   // 1024 CTAs
    conv_f16_mma_kernel<<<grid, 256, SMEM_BYTES>>>(bias, out);
}